// round 14
// baseline (speedup 1.0000x reference)
#include <cuda_runtime.h>
#include <cuda_fp16.h>
#include <cstdint>

// ============================================================================
// HiPPO-LegT scan via chunked GEMM on mma.sync (HMMA fp16, base sm_103).
//   c_t = A c_{t-1} + f_t B ;  out (512, 2048, 64)
// Chunk T=16:  OUT[c][(j,n)] = sum_k X[c][k] * G[(j,n)][k],  K = 80.
// Single fp16 pass (validated: rel_err ~2.87e-4).
// R14: gemm __launch_bounds__(256,3) restores 3 CTAs/SM with the permuted-G
// float4 epilogue (R13 regressed on a reg-count occupancy cliff: 86 regs ->
// 2 CTAs/SM).  prep matmuls widened to all 1024 threads.
// ============================================================================

static constexpr int TCH    = 16;
static constexpr int NCHUNK = 32;
static constexpr int NSEQ   = 2048;
static constexpr int NCOLS  = NSEQ * NCHUNK;   // 65536
static constexpr int KREAL  = 80;
static constexpr int SEQLEN = 512;
static constexpr int KPADB  = 176;             // smem row pitch bytes (88 halves)
static constexpr int MT     = 128;             // X columns per CTA

// ---- device scratch (static; no cudaMalloc) ----
__device__ __align__(16) float   g_sq[3][4096];     // A^2, A^4, A^8
__device__ __align__(16) float   g_Apow16[4096];
__device__ __align__(16) float   g_Kvec[16 * 64];
__device__ __align__(16) __half  g_Gh[1024 * KREAL];
__device__ __align__(16) __half  g_Xh[(size_t)NCOLS * KREAL];

// ---- packed f32x2 helpers ----
__device__ __forceinline__ double fma2(double a, double b, double c) {
    double d; asm("fma.rn.f32x2 %0, %1, %2, %3;" : "=d"(d) : "d"(a), "d"(b), "d"(c)); return d;
}
__device__ __forceinline__ double add2(double a, double b) {
    double d; asm("add.rn.f32x2 %0, %1, %2;" : "=d"(d) : "d"(a), "d"(b)); return d;
}
__device__ __forceinline__ double pack2(float lo, float hi) {
    double d; asm("mov.b64 %0, {%1, %2};" : "=d"(d) : "f"(lo), "f"(hi)); return d;
}
__device__ __forceinline__ void unpack2(double d, float& lo, float& hi) {
    asm("mov.b64 {%0, %1}, %2;" : "=f"(lo), "=f"(hi) : "d"(d));
}

// ---- mma / ldmatrix / cp.async ----
__device__ __forceinline__ uint32_t smem_u32(const void* p) {
    uint32_t a;
    asm("{ .reg .u64 t; cvta.to.shared.u64 t, %1; cvt.u32.u64 %0, t; }" : "=r"(a) : "l"(p));
    return a;
}
__device__ __forceinline__ void mma16816(float* d, const uint32_t* a, uint32_t b0, uint32_t b1) {
    asm volatile(
        "mma.sync.aligned.m16n8k16.row.col.f32.f16.f16.f32 "
        "{%0,%1,%2,%3}, {%4,%5,%6,%7}, {%8,%9}, {%0,%1,%2,%3};\n"
        : "+f"(d[0]), "+f"(d[1]), "+f"(d[2]), "+f"(d[3])
        : "r"(a[0]), "r"(a[1]), "r"(a[2]), "r"(a[3]), "r"(b0), "r"(b1));
}
__device__ __forceinline__ void ldsm_x4(uint32_t* r, uint32_t addr) {
    asm volatile("ldmatrix.sync.aligned.m8n8.x4.shared.b16 {%0,%1,%2,%3}, [%4];"
                 : "=r"(r[0]), "=r"(r[1]), "=r"(r[2]), "=r"(r[3]) : "r"(addr));
}
__device__ __forceinline__ void cp_async16(uint32_t smem, const void* g) {
    asm volatile("cp.async.cg.shared.global [%0], [%1], 16;" :: "r"(smem), "l"(g));
}
__device__ __forceinline__ void cp_commit() { asm volatile("cp.async.commit_group;" ::: "memory"); }
__device__ __forceinline__ void cp_wait0()  { asm volatile("cp.async.wait_group 0;"  ::: "memory"); }

// ---- 64x64x64 matmul D = L @ R with ALL 1024 threads ----
// Thread t: row r = t>>4, cols c4 = (t&15)*4; one float4 accumulator.
// D must not alias L or R.
__device__ __forceinline__ void mm64w(const float* __restrict__ L,
                                      const float* __restrict__ R,
                                      float* __restrict__ D, int t) {
    const int r  = t >> 4;
    const int c4 = t & 15;
    const float4* R4 = reinterpret_cast<const float4*>(R);
    float4 acc = make_float4(0.f, 0.f, 0.f, 0.f);
    float4 bcc = make_float4(0.f, 0.f, 0.f, 0.f);
    #pragma unroll 8
    for (int m = 0; m < 64; m += 2) {
        const float a0 = L[r * 64 + m];
        const float a1 = L[r * 64 + m + 1];
        const float4 b0 = R4[m * 16 + c4];
        const float4 b1 = R4[(m + 1) * 16 + c4];
        acc.x = fmaf(a0, b0.x, acc.x); acc.y = fmaf(a0, b0.y, acc.y);
        acc.z = fmaf(a0, b0.z, acc.z); acc.w = fmaf(a0, b0.w, acc.w);
        bcc.x = fmaf(a1, b1.x, bcc.x); bcc.y = fmaf(a1, b1.y, bcc.y);
        bcc.z = fmaf(a1, b1.z, bcc.z); bcc.w = fmaf(a1, b1.w, bcc.w);
    }
    acc.x += bcc.x; acc.y += bcc.y; acc.z += bcc.z; acc.w += bcc.w;
    reinterpret_cast<float4*>(D)[r * 16 + c4] = acc;
    __syncthreads();
}

// ============================================================================
// prep_a: 1 CTA x 1024 threads.  Squares chain + K-vector doubling.
// ============================================================================
__global__ __launch_bounds__(1024) void prep_a_kernel(const float* __restrict__ A,
                                                      const float* __restrict__ Bvec) {
    __shared__ __align__(16) float sX[4096];
    __shared__ __align__(16) float sY[4096];
    __shared__ __align__(16) float sK[16 * 64];
    const int t = threadIdx.x;

    for (int i = t; i < 4096; i += 1024) sX[i] = A[i];
    if (t < 64) sK[t] = Bvec[t];
    __syncthreads();

    if (t < 64) {                                 // K1 = A K0
        float s = 0.f;
        #pragma unroll
        for (int m = 0; m < 64; m++) s = fmaf(sX[t * 64 + m], sK[m], s);
        sK[64 + t] = s;
    }
    __syncthreads();

    mm64w(sX, sX, sY, t);                         // S2
    for (int i = t; i < 4096; i += 1024) g_sq[0][i] = sY[i];

    if (t < 128) {                                // K2,K3 = S2 {K0,K1}
        const int v = t >> 6, n = t & 63;
        float s = 0.f;
        #pragma unroll
        for (int m = 0; m < 64; m++) s = fmaf(sY[n * 64 + m], sK[v * 64 + m], s);
        sK[(2 + v) * 64 + n] = s;
    }
    __syncthreads();

    mm64w(sY, sY, sX, t);                         // S4
    for (int i = t; i < 4096; i += 1024) g_sq[1][i] = sX[i];

    if (t < 256) {                                // K4..7 = S4 K0..3
        const int v = t >> 6, n = t & 63;
        float s = 0.f;
        #pragma unroll
        for (int m = 0; m < 64; m++) s = fmaf(sX[n * 64 + m], sK[v * 64 + m], s);
        sK[(4 + v) * 64 + n] = s;
    }
    __syncthreads();

    mm64w(sX, sX, sY, t);                         // S8
    for (int i = t; i < 4096; i += 1024) g_sq[2][i] = sY[i];

    if (t < 512) {                                // K8..15 = S8 K0..7
        const int v = t >> 6, n = t & 63;
        float s = 0.f;
        #pragma unroll
        for (int m = 0; m < 64; m++) s = fmaf(sY[n * 64 + m], sK[v * 64 + m], s);
        sK[(8 + v) * 64 + n] = s;
    }
    __syncthreads();

    mm64w(sY, sY, sX, t);                         // S16
    for (int i = t; i < 4096; i += 1024) g_Apow16[i] = sX[i];
    g_Kvec[t & 1023] = sK[t & 1023];
}

// ============================================================================
// prep_b: 16 CTAs x 1024 threads.  CTA j: A^(j+1) from {A,S2,S4,S8},
// writes 64 PERMUTED G rows.
// ============================================================================
__global__ __launch_bounds__(1024) void prep_b_kernel(const float* __restrict__ A) {
    __shared__ __align__(16) float sBuf[3][4096];
    const int t = threadIdx.x;
    const int j = blockIdx.x;
    const int p = j + 1;

    const float* fsrc[4];
    int nf = 0;
    if (p == 16) { fsrc[0] = g_sq[2]; fsrc[1] = g_sq[2]; nf = 2; }
    else {
        if (p & 1) fsrc[nf++] = A;
        if (p & 2) fsrc[nf++] = g_sq[0];
        if (p & 4) fsrc[nf++] = g_sq[1];
        if (p & 8) fsrc[nf++] = g_sq[2];
    }

    for (int i = t; i < 4096; i += 1024) sBuf[0][i] = fsrc[0][i];
    __syncthreads();

    int cur = 0;
    for (int f = 1; f < nf; f++) {
        for (int i = t; i < 4096; i += 1024) sBuf[2][i] = fsrc[f][i];
        __syncthreads();
        mm64w(sBuf[cur], sBuf[2], sBuf[cur ^ 1], t);
        cur ^= 1;
    }
    const float* P = sBuf[cur];

    // G rows, PERMUTED: physical pn -> logical n = 16*((pn&7)>>1)+2*(pn>>3)+(pn&1)
    for (int idx = t; idx < 64 * KREAL; idx += 1024) {
        const int pn = idx / KREAL, k = idx % KREAL;
        const int n = 16 * ((pn & 7) >> 1) + 2 * (pn >> 3) + (pn & 1);
        float v;
        if (k < 64) v = P[n * 64 + k];
        else {
            const int d = j - (k - 64);
            v = (d < 0) ? 0.0f : g_Kvec[d * 64 + n];
        }
        g_Gh[(size_t)(j * 64 + pn) * KREAL + k] = __float2half(v);
    }
}

// ============================================================================
// Phase 1: boundary scan (fp32, f32x2) + X build (fp16). 2048 x 64.
// ============================================================================
__global__ __launch_bounds__(64) void phase1_kernel(const float* __restrict__ xin) {
    const int seq = blockIdx.x, n = threadIdx.x;
    __shared__ __align__(16) float c_sm[2][64];
    __shared__ __align__(16) float f_sm[2][16];

    double a16[32];
    {
        const double* r = reinterpret_cast<const double*>(&g_Apow16[n * 64]);
        #pragma unroll
        for (int i = 0; i < 32; i++) a16[i] = r[i];
    }
    double wp[8];
    #pragma unroll
    for (int i = 0; i < 8; i++)
        wp[i] = pack2(g_Kvec[(15 - 2 * i) * 64 + n], g_Kvec[(14 - 2 * i) * 64 + n]);

    float cmy = 0.0f;
    c_sm[0][n] = 0.0f;

    for (int k = 0; k < NCHUNK; k++) {
        const int buf = k & 1;
        const size_t col = (size_t)k * NSEQ + seq;
        g_Xh[col * KREAL + n] = __float2half(cmy);
        if (n < 16) {
            const float f = xin[(size_t)seq * SEQLEN + k * TCH + n];
            f_sm[buf][n] = f;
            g_Xh[col * KREAL + 64 + n] = __float2half(f);
        }
        __syncthreads();

        const double2* cp = reinterpret_cast<const double2*>(c_sm[buf]);
        double acc0 = 0.0, acc1 = 0.0, acc2 = 0.0, acc3 = 0.0;
        #pragma unroll
        for (int i = 0; i < 8; i++) {
            const double2 ca = cp[2 * i], cb = cp[2 * i + 1];
            acc0 = fma2(a16[4 * i],     ca.x, acc0);
            acc1 = fma2(a16[4 * i + 1], ca.y, acc1);
            acc2 = fma2(a16[4 * i + 2], cb.x, acc2);
            acc3 = fma2(a16[4 * i + 3], cb.y, acc3);
        }
        const double* fp = reinterpret_cast<const double*>(f_sm[buf]);
        acc0 = fma2(wp[0], fp[0], acc0); acc1 = fma2(wp[1], fp[1], acc1);
        acc2 = fma2(wp[2], fp[2], acc2); acc3 = fma2(wp[3], fp[3], acc3);
        acc0 = fma2(wp[4], fp[4], acc0); acc1 = fma2(wp[5], fp[5], acc1);
        acc2 = fma2(wp[6], fp[6], acc2); acc3 = fma2(wp[7], fp[7], acc3);

        const double s = add2(add2(acc0, acc1), add2(acc2, acc3));
        float x, y;
        unpack2(s, x, y);
        cmy = x + y;
        c_sm[buf ^ 1][n] = cmy;
    }
}

// ============================================================================
// GEMM: grid (512, 8) x 256 thr, __launch_bounds__(256, 3) -> regs <= 85,
// 3 CTAs/SM.  CTA: 128 X-cols x 2 jt, ONE barrier.
// Arena 45056 B: [Xh 22528 | G(j0) 11264 | G(j0+1) 11264].
// Permuted G -> each thread's 16 accs per row contiguous -> float4 stores.
// ============================================================================
__global__ __launch_bounds__(256, 3) void gemm_kernel(float* __restrict__ out) {
    __shared__ __align__(16) char arena[45056];

    const int tid = threadIdx.x;
    const int w = tid >> 5, l = tid & 31;
    const int mbase = blockIdx.x * MT;
    const int j0    = blockIdx.y * 2;
    const uint32_t base = smem_u32(arena);

    for (int c = tid; c < 1280; c += 256) {
        const int row = c / 10, part = c % 10;
        cp_async16(base + row * KPADB + part * 16,
                   (const char*)(g_Xh + (size_t)(mbase + row) * KREAL) + part * 16);
    }
    for (int c = tid; c < 1280; c += 256) {
        const int g = c / 640, rem = c % 640;
        const int row = rem / 10, part = rem % 10;
        cp_async16(base + 22528 + g * 11264 + row * KPADB + part * 16,
                   (const char*)(g_Gh + (size_t)((j0 + g) * 64 + row) * KREAL) + part * 16);
    }
    cp_commit(); cp_wait0();
    __syncthreads();

    const int jl = w >> 2;
    const int mq = w & 3;
    const int jt = j0 + jl;

    const uint32_t aoff = base + (uint32_t)(mq * 32 + (l & 15)) * KPADB + ((l >> 4) * 16);
    const uint32_t gbuf = base + 22528 + jl * 11264;
    const uint32_t boff = gbuf + (uint32_t)((l & 7) + ((l & 16) >> 1)) * KPADB + ((l & 8) << 1);

    float acc[2][8][4];
    #pragma unroll
    for (int mt = 0; mt < 2; mt++)
        #pragma unroll
        for (int nt = 0; nt < 8; nt++)
            #pragma unroll
            for (int q = 0; q < 4; q++) acc[mt][nt][q] = 0.0f;

    #pragma unroll
    for (int ks = 0; ks < 5; ks++) {
        uint32_t bh[4][4];
        #pragma unroll
        for (int p = 0; p < 4; p++)
            ldsm_x4(bh[p], boff + p * (16 * KPADB) + ks * 32);
        #pragma unroll
        for (int mt = 0; mt < 2; mt++) {
            uint32_t a4[4];
            ldsm_x4(a4, aoff + mt * (16 * KPADB) + ks * 32);
            #pragma unroll
            for (int p = 0; p < 4; p++)
                #pragma unroll
                for (int hh = 0; hh < 2; hh++)
                    mma16816(acc[mt][p * 2 + hh], a4, bh[p][2 * hh], bh[p][2 * hh + 1]);
        }
    }

    const int chunk = mbase >> 11;
    const int seqb  = mbase & 2047;
    const int q     = l & 3;
    float* obase = out + (size_t)(chunk * TCH + jt) * NSEQ * 64 + 16 * q;
    #pragma unroll
    for (int mt = 0; mt < 2; mt++)
        #pragma unroll
        for (int s = 0; s < 2; s++) {
            const int m = mq * 32 + mt * 16 + (l >> 2) + s * 8;
            float* ob = obase + (size_t)(seqb + m) * 64;
            #pragma unroll
            for (int j4 = 0; j4 < 4; j4++) {
                float4 v = make_float4(acc[mt][2 * j4][2 * s],
                                       acc[mt][2 * j4][2 * s + 1],
                                       acc[mt][2 * j4 + 1][2 * s],
                                       acc[mt][2 * j4 + 1][2 * s + 1]);
                __stcs(reinterpret_cast<float4*>(ob + 4 * j4), v);
            }
        }
}

// ============================================================================
extern "C" void kernel_launch(void* const* d_in, const int* in_sizes, int n_in,
                              void* d_out, int out_size) {
    const float* xin  = (const float*)d_in[0];  // (16,128,512)
    const float* Amat = (const float*)d_in[1];  // (64,64)
    const float* Bvec = (const float*)d_in[2];  // (64,)
    float* out = (float*)d_out;                 // (512,16,128,64)

    prep_a_kernel<<<1, 1024>>>(Amat, Bvec);
    prep_b_kernel<<<16, 1024>>>(Amat);
    phase1_kernel<<<NSEQ, 64>>>(xin);
    dim3 ggrid(NCOLS / MT, 8);                  // (512, 8)
    gemm_kernel<<<ggrid, 256>>>(out);
}

// round 15
// speedup vs baseline: 1.3851x; 1.3851x over previous
#include <cuda_runtime.h>
#include <cuda_fp16.h>
#include <cstdint>

// ============================================================================
// HiPPO-LegT scan via chunked GEMM on mma.sync (HMMA fp16, base sm_103).
//   c_t = A c_{t-1} + f_t B ;  out (512, 2048, 64)
// Chunk T=16:  OUT[c][(j,n)] = sum_k X[c][k] * G[(j,n)][k],  K = 80.
// Single fp16 pass (validated: rel_err ~2.87e-4).
// R15: DENSE-SECTOR permuted epilogue.  G permutation chosen so each lane
// quad writes a contiguous 64B block per STG.128:
//   physical pn = 16a+8b+2q+e  ->  logical n = 16a+4q+2b+e
// (R14's permutation put thread chunks at 64B lane stride -> half-filled
// 32B sectors -> 2x store transactions; that was the whole regression.)
// ============================================================================

static constexpr int TCH    = 16;
static constexpr int NCHUNK = 32;
static constexpr int NSEQ   = 2048;
static constexpr int NCOLS  = NSEQ * NCHUNK;   // 65536
static constexpr int KREAL  = 80;
static constexpr int SEQLEN = 512;
static constexpr int KPADB  = 176;             // smem row pitch bytes (88 halves)
static constexpr int MT     = 128;             // X columns per CTA

// ---- device scratch (static; no cudaMalloc) ----
__device__ __align__(16) float   g_sq[3][4096];     // A^2, A^4, A^8
__device__ __align__(16) float   g_Apow16[4096];
__device__ __align__(16) float   g_Kvec[16 * 64];
__device__ __align__(16) __half  g_Gh[1024 * KREAL];
__device__ __align__(16) __half  g_Xh[(size_t)NCOLS * KREAL];

// ---- packed f32x2 helpers ----
__device__ __forceinline__ double fma2(double a, double b, double c) {
    double d; asm("fma.rn.f32x2 %0, %1, %2, %3;" : "=d"(d) : "d"(a), "d"(b), "d"(c)); return d;
}
__device__ __forceinline__ double add2(double a, double b) {
    double d; asm("add.rn.f32x2 %0, %1, %2;" : "=d"(d) : "d"(a), "d"(b)); return d;
}
__device__ __forceinline__ double pack2(float lo, float hi) {
    double d; asm("mov.b64 %0, {%1, %2};" : "=d"(d) : "f"(lo), "f"(hi)); return d;
}
__device__ __forceinline__ void unpack2(double d, float& lo, float& hi) {
    asm("mov.b64 {%0, %1}, %2;" : "=f"(lo), "=f"(hi) : "d"(d));
}

// ---- mma / ldmatrix / cp.async ----
__device__ __forceinline__ uint32_t smem_u32(const void* p) {
    uint32_t a;
    asm("{ .reg .u64 t; cvta.to.shared.u64 t, %1; cvt.u32.u64 %0, t; }" : "=r"(a) : "l"(p));
    return a;
}
__device__ __forceinline__ void mma16816(float* d, const uint32_t* a, uint32_t b0, uint32_t b1) {
    asm volatile(
        "mma.sync.aligned.m16n8k16.row.col.f32.f16.f16.f32 "
        "{%0,%1,%2,%3}, {%4,%5,%6,%7}, {%8,%9}, {%0,%1,%2,%3};\n"
        : "+f"(d[0]), "+f"(d[1]), "+f"(d[2]), "+f"(d[3])
        : "r"(a[0]), "r"(a[1]), "r"(a[2]), "r"(a[3]), "r"(b0), "r"(b1));
}
__device__ __forceinline__ void ldsm_x4(uint32_t* r, uint32_t addr) {
    asm volatile("ldmatrix.sync.aligned.m8n8.x4.shared.b16 {%0,%1,%2,%3}, [%4];"
                 : "=r"(r[0]), "=r"(r[1]), "=r"(r[2]), "=r"(r[3]) : "r"(addr));
}
__device__ __forceinline__ void cp_async16(uint32_t smem, const void* g) {
    asm volatile("cp.async.cg.shared.global [%0], [%1], 16;" :: "r"(smem), "l"(g));
}
__device__ __forceinline__ void cp_commit() { asm volatile("cp.async.commit_group;" ::: "memory"); }
__device__ __forceinline__ void cp_wait0()  { asm volatile("cp.async.wait_group 0;"  ::: "memory"); }

// ---- 64x64x64 matmul D = L @ R with ALL 1024 threads ----
__device__ __forceinline__ void mm64w(const float* __restrict__ L,
                                      const float* __restrict__ R,
                                      float* __restrict__ D, int t) {
    const int r  = t >> 4;
    const int c4 = t & 15;
    const float4* R4 = reinterpret_cast<const float4*>(R);
    float4 acc = make_float4(0.f, 0.f, 0.f, 0.f);
    float4 bcc = make_float4(0.f, 0.f, 0.f, 0.f);
    #pragma unroll 8
    for (int m = 0; m < 64; m += 2) {
        const float a0 = L[r * 64 + m];
        const float a1 = L[r * 64 + m + 1];
        const float4 b0 = R4[m * 16 + c4];
        const float4 b1 = R4[(m + 1) * 16 + c4];
        acc.x = fmaf(a0, b0.x, acc.x); acc.y = fmaf(a0, b0.y, acc.y);
        acc.z = fmaf(a0, b0.z, acc.z); acc.w = fmaf(a0, b0.w, acc.w);
        bcc.x = fmaf(a1, b1.x, bcc.x); bcc.y = fmaf(a1, b1.y, bcc.y);
        bcc.z = fmaf(a1, b1.z, bcc.z); bcc.w = fmaf(a1, b1.w, bcc.w);
    }
    acc.x += bcc.x; acc.y += bcc.y; acc.z += bcc.z; acc.w += bcc.w;
    reinterpret_cast<float4*>(D)[r * 16 + c4] = acc;
    __syncthreads();
}

// ============================================================================
// prep_a: 1 CTA x 1024 threads.  Squares chain + K-vector doubling.
// ============================================================================
__global__ __launch_bounds__(1024) void prep_a_kernel(const float* __restrict__ A,
                                                      const float* __restrict__ Bvec) {
    __shared__ __align__(16) float sX[4096];
    __shared__ __align__(16) float sY[4096];
    __shared__ __align__(16) float sK[16 * 64];
    const int t = threadIdx.x;

    for (int i = t; i < 4096; i += 1024) sX[i] = A[i];
    if (t < 64) sK[t] = Bvec[t];
    __syncthreads();

    if (t < 64) {                                 // K1 = A K0
        float s = 0.f;
        #pragma unroll
        for (int m = 0; m < 64; m++) s = fmaf(sX[t * 64 + m], sK[m], s);
        sK[64 + t] = s;
    }
    __syncthreads();

    mm64w(sX, sX, sY, t);                         // S2
    for (int i = t; i < 4096; i += 1024) g_sq[0][i] = sY[i];

    if (t < 128) {                                // K2,K3 = S2 {K0,K1}
        const int v = t >> 6, n = t & 63;
        float s = 0.f;
        #pragma unroll
        for (int m = 0; m < 64; m++) s = fmaf(sY[n * 64 + m], sK[v * 64 + m], s);
        sK[(2 + v) * 64 + n] = s;
    }
    __syncthreads();

    mm64w(sY, sY, sX, t);                         // S4
    for (int i = t; i < 4096; i += 1024) g_sq[1][i] = sX[i];

    if (t < 256) {                                // K4..7 = S4 K0..3
        const int v = t >> 6, n = t & 63;
        float s = 0.f;
        #pragma unroll
        for (int m = 0; m < 64; m++) s = fmaf(sX[n * 64 + m], sK[v * 64 + m], s);
        sK[(4 + v) * 64 + n] = s;
    }
    __syncthreads();

    mm64w(sX, sX, sY, t);                         // S8
    for (int i = t; i < 4096; i += 1024) g_sq[2][i] = sY[i];

    if (t < 512) {                                // K8..15 = S8 K0..7
        const int v = t >> 6, n = t & 63;
        float s = 0.f;
        #pragma unroll
        for (int m = 0; m < 64; m++) s = fmaf(sY[n * 64 + m], sK[v * 64 + m], s);
        sK[(8 + v) * 64 + n] = s;
    }
    __syncthreads();

    mm64w(sY, sY, sX, t);                         // S16
    for (int i = t; i < 4096; i += 1024) g_Apow16[i] = sX[i];
    g_Kvec[t & 1023] = sK[t & 1023];
}

// ============================================================================
// prep_b: 16 CTAs x 1024 threads.  CTA j: A^(j+1) from {A,S2,S4,S8},
// writes 64 DENSE-PERMUTED G rows.
// ============================================================================
__global__ __launch_bounds__(1024) void prep_b_kernel(const float* __restrict__ A) {
    __shared__ __align__(16) float sBuf[3][4096];
    const int t = threadIdx.x;
    const int j = blockIdx.x;
    const int p = j + 1;

    const float* fsrc[4];
    int nf = 0;
    if (p == 16) { fsrc[0] = g_sq[2]; fsrc[1] = g_sq[2]; nf = 2; }
    else {
        if (p & 1) fsrc[nf++] = A;
        if (p & 2) fsrc[nf++] = g_sq[0];
        if (p & 4) fsrc[nf++] = g_sq[1];
        if (p & 8) fsrc[nf++] = g_sq[2];
    }

    for (int i = t; i < 4096; i += 1024) sBuf[0][i] = fsrc[0][i];
    __syncthreads();

    int cur = 0;
    for (int f = 1; f < nf; f++) {
        for (int i = t; i < 4096; i += 1024) sBuf[2][i] = fsrc[f][i];
        __syncthreads();
        mm64w(sBuf[cur], sBuf[2], sBuf[cur ^ 1], t);
        cur ^= 1;
    }
    const float* P = sBuf[cur];

    // G rows, DENSE-PERMUTED:
    // pn = 16a + 8b + 2q + e  ->  n = 16a + 4q + 2b + e
    for (int idx = t; idx < 64 * KREAL; idx += 1024) {
        const int pn = idx / KREAL, k = idx % KREAL;
        const int a = pn >> 4, b = (pn >> 3) & 1, q = (pn >> 1) & 3, e = pn & 1;
        const int n = 16 * a + 4 * q + 2 * b + e;
        float v;
        if (k < 64) v = P[n * 64 + k];
        else {
            const int d = j - (k - 64);
            v = (d < 0) ? 0.0f : g_Kvec[d * 64 + n];
        }
        g_Gh[(size_t)(j * 64 + pn) * KREAL + k] = __float2half(v);
    }
}

// ============================================================================
// Phase 1: boundary scan (fp32, f32x2) + X build (fp16). 2048 x 64.
// ============================================================================
__global__ __launch_bounds__(64) void phase1_kernel(const float* __restrict__ xin) {
    const int seq = blockIdx.x, n = threadIdx.x;
    __shared__ __align__(16) float c_sm[2][64];
    __shared__ __align__(16) float f_sm[2][16];

    double a16[32];
    {
        const double* r = reinterpret_cast<const double*>(&g_Apow16[n * 64]);
        #pragma unroll
        for (int i = 0; i < 32; i++) a16[i] = r[i];
    }
    double wp[8];
    #pragma unroll
    for (int i = 0; i < 8; i++)
        wp[i] = pack2(g_Kvec[(15 - 2 * i) * 64 + n], g_Kvec[(14 - 2 * i) * 64 + n]);

    float cmy = 0.0f;
    c_sm[0][n] = 0.0f;

    for (int k = 0; k < NCHUNK; k++) {
        const int buf = k & 1;
        const size_t col = (size_t)k * NSEQ + seq;
        g_Xh[col * KREAL + n] = __float2half(cmy);
        if (n < 16) {
            const float f = xin[(size_t)seq * SEQLEN + k * TCH + n];
            f_sm[buf][n] = f;
            g_Xh[col * KREAL + 64 + n] = __float2half(f);
        }
        __syncthreads();

        const double2* cp = reinterpret_cast<const double2*>(c_sm[buf]);
        double acc0 = 0.0, acc1 = 0.0, acc2 = 0.0, acc3 = 0.0;
        #pragma unroll
        for (int i = 0; i < 8; i++) {
            const double2 ca = cp[2 * i], cb = cp[2 * i + 1];
            acc0 = fma2(a16[4 * i],     ca.x, acc0);
            acc1 = fma2(a16[4 * i + 1], ca.y, acc1);
            acc2 = fma2(a16[4 * i + 2], cb.x, acc2);
            acc3 = fma2(a16[4 * i + 3], cb.y, acc3);
        }
        const double* fp = reinterpret_cast<const double*>(f_sm[buf]);
        acc0 = fma2(wp[0], fp[0], acc0); acc1 = fma2(wp[1], fp[1], acc1);
        acc2 = fma2(wp[2], fp[2], acc2); acc3 = fma2(wp[3], fp[3], acc3);
        acc0 = fma2(wp[4], fp[4], acc0); acc1 = fma2(wp[5], fp[5], acc1);
        acc2 = fma2(wp[6], fp[6], acc2); acc3 = fma2(wp[7], fp[7], acc3);

        const double s = add2(add2(acc0, acc1), add2(acc2, acc3));
        float x, y;
        unpack2(s, x, y);
        cmy = x + y;
        c_sm[buf ^ 1][n] = cmy;
    }
}

// ============================================================================
// GEMM: grid (512, 8) x 256 thr, __launch_bounds__(256, 3).
// CTA: 128 X-cols x 2 jt, ONE barrier.
// Arena 45056 B: [Xh 22528 | G(j0) 11264 | G(j0+1) 11264].
// Dense-permuted G: per (mt,s,a) a float4 at column 16a+4q; lane quads write
// contiguous 64B blocks -> fully dense sectors, 16 STG.128 per thread.
// ============================================================================
__global__ __launch_bounds__(256, 3) void gemm_kernel(float* __restrict__ out) {
    __shared__ __align__(16) char arena[45056];

    const int tid = threadIdx.x;
    const int w = tid >> 5, l = tid & 31;
    const int mbase = blockIdx.x * MT;
    const int j0    = blockIdx.y * 2;
    const uint32_t base = smem_u32(arena);

    for (int c = tid; c < 1280; c += 256) {
        const int row = c / 10, part = c % 10;
        cp_async16(base + row * KPADB + part * 16,
                   (const char*)(g_Xh + (size_t)(mbase + row) * KREAL) + part * 16);
    }
    for (int c = tid; c < 1280; c += 256) {
        const int g = c / 640, rem = c % 640;
        const int row = rem / 10, part = rem % 10;
        cp_async16(base + 22528 + g * 11264 + row * KPADB + part * 16,
                   (const char*)(g_Gh + (size_t)((j0 + g) * 64 + row) * KREAL) + part * 16);
    }
    cp_commit(); cp_wait0();
    __syncthreads();

    const int jl = w >> 2;
    const int mq = w & 3;
    const int jt = j0 + jl;

    const uint32_t aoff = base + (uint32_t)(mq * 32 + (l & 15)) * KPADB + ((l >> 4) * 16);
    const uint32_t gbuf = base + 22528 + jl * 11264;
    const uint32_t boff = gbuf + (uint32_t)((l & 7) + ((l & 16) >> 1)) * KPADB + ((l & 8) << 1);

    float acc[2][8][4];
    #pragma unroll
    for (int mt = 0; mt < 2; mt++)
        #pragma unroll
        for (int nt = 0; nt < 8; nt++)
            #pragma unroll
            for (int q = 0; q < 4; q++) acc[mt][nt][q] = 0.0f;

    #pragma unroll
    for (int ks = 0; ks < 5; ks++) {
        uint32_t bh[4][4];
        #pragma unroll
        for (int p = 0; p < 4; p++)
            ldsm_x4(bh[p], boff + p * (16 * KPADB) + ks * 32);
        #pragma unroll
        for (int mt = 0; mt < 2; mt++) {
            uint32_t a4[4];
            ldsm_x4(a4, aoff + mt * (16 * KPADB) + ks * 32);
            #pragma unroll
            for (int p = 0; p < 4; p++)
                #pragma unroll
                for (int hh = 0; hh < 2; hh++)
                    mma16816(acc[mt][p * 2 + hh], a4, bh[p][2 * hh], bh[p][2 * hh + 1]);
        }
    }

    // ---- epilogue: dense 64B quad blocks ----
    const int chunk = mbase >> 11;
    const int seqb  = mbase & 2047;
    const int q     = l & 3;
    float* obase = out + (size_t)(chunk * TCH + jt) * NSEQ * 64 + 4 * q;
    #pragma unroll
    for (int mt = 0; mt < 2; mt++)
        #pragma unroll
        for (int s = 0; s < 2; s++) {
            const int m = mq * 32 + mt * 16 + (l >> 2) + s * 8;
            float* ob = obase + (size_t)(seqb + m) * 64;
            #pragma unroll
            for (int a = 0; a < 4; a++) {
                float4 v = make_float4(acc[mt][2 * a][2 * s],
                                       acc[mt][2 * a][2 * s + 1],
                                       acc[mt][2 * a + 1][2 * s],
                                       acc[mt][2 * a + 1][2 * s + 1]);
                __stcs(reinterpret_cast<float4*>(ob + 16 * a), v);
            }
        }
}

// ============================================================================
extern "C" void kernel_launch(void* const* d_in, const int* in_sizes, int n_in,
                              void* d_out, int out_size) {
    const float* xin  = (const float*)d_in[0];  // (16,128,512)
    const float* Amat = (const float*)d_in[1];  // (64,64)
    const float* Bvec = (const float*)d_in[2];  // (64,)
    float* out = (float*)d_out;                 // (512,16,128,64)

    prep_a_kernel<<<1, 1024>>>(Amat, Bvec);
    prep_b_kernel<<<16, 1024>>>(Amat);
    phase1_kernel<<<NSEQ, 64>>>(xin);
    dim3 ggrid(NCOLS / MT, 8);                  // (512, 8)
    gemm_kernel<<<ggrid, 256>>>(out);
}

// round 16
// speedup vs baseline: 1.6434x; 1.1865x over previous
#include <cuda_runtime.h>
#include <cuda_fp16.h>
#include <cstdint>

// ============================================================================
// HiPPO-LegT scan via chunked GEMM on mma.sync (HMMA fp16, base sm_103).
//   c_t = A c_{t-1} + f_t B ;  out (512, 2048, 64)
// Chunk T=16:  OUT[c][(j,n)] = sum_k X[c][k] * G[(j,n)][k],  K = 80.
// Single fp16 pass (validated: rel_err ~2.87e-4).
// R16: prep matmuls back to mm64 (4x4 register blocking -- mm64w was
// LDS-instruction-bound, the R14/R15 "others" regression).  prep_b and
// phase1 merged into ONE launch (mutually independent, both gated only on
// prep_a).  GEMM keeps R15's dense-sector permuted float4 epilogue.
// ============================================================================

static constexpr int TCH    = 16;
static constexpr int NCHUNK = 32;
static constexpr int NSEQ   = 2048;
static constexpr int NCOLS  = NSEQ * NCHUNK;   // 65536
static constexpr int KREAL  = 80;
static constexpr int SEQLEN = 512;
static constexpr int KPADB  = 176;             // smem row pitch bytes (88 halves)
static constexpr int MT     = 128;             // X columns per CTA

// ---- device scratch (static; no cudaMalloc) ----
__device__ __align__(16) float   g_sq[3][4096];     // A^2, A^4, A^8
__device__ __align__(16) float   g_Apow16[4096];
__device__ __align__(16) float   g_Kvec[16 * 64];
__device__ __align__(16) __half  g_Gh[1024 * KREAL];
__device__ __align__(16) __half  g_Xh[(size_t)NCOLS * KREAL];

// ---- packed f32x2 helpers ----
__device__ __forceinline__ double fma2(double a, double b, double c) {
    double d; asm("fma.rn.f32x2 %0, %1, %2, %3;" : "=d"(d) : "d"(a), "d"(b), "d"(c)); return d;
}
__device__ __forceinline__ double add2(double a, double b) {
    double d; asm("add.rn.f32x2 %0, %1, %2;" : "=d"(d) : "d"(a), "d"(b)); return d;
}
__device__ __forceinline__ double pack2(float lo, float hi) {
    double d; asm("mov.b64 %0, {%1, %2};" : "=d"(d) : "f"(lo), "f"(hi)); return d;
}
__device__ __forceinline__ void unpack2(double d, float& lo, float& hi) {
    asm("mov.b64 {%0, %1}, %2;" : "=f"(lo), "=f"(hi) : "d"(d));
}

// ---- mma / ldmatrix / cp.async ----
__device__ __forceinline__ uint32_t smem_u32(const void* p) {
    uint32_t a;
    asm("{ .reg .u64 t; cvta.to.shared.u64 t, %1; cvt.u32.u64 %0, t; }" : "=r"(a) : "l"(p));
    return a;
}
__device__ __forceinline__ void mma16816(float* d, const uint32_t* a, uint32_t b0, uint32_t b1) {
    asm volatile(
        "mma.sync.aligned.m16n8k16.row.col.f32.f16.f16.f32 "
        "{%0,%1,%2,%3}, {%4,%5,%6,%7}, {%8,%9}, {%0,%1,%2,%3};\n"
        : "+f"(d[0]), "+f"(d[1]), "+f"(d[2]), "+f"(d[3])
        : "r"(a[0]), "r"(a[1]), "r"(a[2]), "r"(a[3]), "r"(b0), "r"(b1));
}
__device__ __forceinline__ void ldsm_x4(uint32_t* r, uint32_t addr) {
    asm volatile("ldmatrix.sync.aligned.m8n8.x4.shared.b16 {%0,%1,%2,%3}, [%4];"
                 : "=r"(r[0]), "=r"(r[1]), "=r"(r[2]), "=r"(r[3]) : "r"(addr));
}
__device__ __forceinline__ void cp_async16(uint32_t smem, const void* g) {
    asm volatile("cp.async.cg.shared.global [%0], [%1], 16;" :: "r"(smem), "l"(g));
}
__device__ __forceinline__ void cp_commit() { asm volatile("cp.async.commit_group;" ::: "memory"); }
__device__ __forceinline__ void cp_wait0()  { asm volatile("cp.async.wait_group 0;"  ::: "memory"); }

// ---- register-blocked 64x64x64 matmul: D = L @ R, 256 threads (all used) ----
__device__ __forceinline__ void mm64(const float* __restrict__ L,
                                     const float* __restrict__ R,
                                     float* __restrict__ D, int t) {
    const int r0 = (t >> 4) * 4;
    const int c4 = (t & 15);
    const float4* L4 = reinterpret_cast<const float4*>(L);
    const float4* R4 = reinterpret_cast<const float4*>(R);
    float4 acc0 = make_float4(0.f, 0.f, 0.f, 0.f);
    float4 acc1 = acc0, acc2 = acc0, acc3 = acc0;
    #pragma unroll
    for (int v = 0; v < 16; v++) {
        const float4 a0 = L4[(r0 + 0) * 16 + v];
        const float4 a1 = L4[(r0 + 1) * 16 + v];
        const float4 a2 = L4[(r0 + 2) * 16 + v];
        const float4 a3 = L4[(r0 + 3) * 16 + v];
        const float4 b0 = R4[(4 * v + 0) * 16 + c4];
        const float4 b1 = R4[(4 * v + 1) * 16 + c4];
        const float4 b2 = R4[(4 * v + 2) * 16 + c4];
        const float4 b3 = R4[(4 * v + 3) * 16 + c4];
        acc0.x = fmaf(a0.x, b0.x, acc0.x); acc0.y = fmaf(a0.x, b0.y, acc0.y);
        acc0.z = fmaf(a0.x, b0.z, acc0.z); acc0.w = fmaf(a0.x, b0.w, acc0.w);
        acc0.x = fmaf(a0.y, b1.x, acc0.x); acc0.y = fmaf(a0.y, b1.y, acc0.y);
        acc0.z = fmaf(a0.y, b1.z, acc0.z); acc0.w = fmaf(a0.y, b1.w, acc0.w);
        acc0.x = fmaf(a0.z, b2.x, acc0.x); acc0.y = fmaf(a0.z, b2.y, acc0.y);
        acc0.z = fmaf(a0.z, b2.z, acc0.z); acc0.w = fmaf(a0.z, b2.w, acc0.w);
        acc0.x = fmaf(a0.w, b3.x, acc0.x); acc0.y = fmaf(a0.w, b3.y, acc0.y);
        acc0.z = fmaf(a0.w, b3.z, acc0.z); acc0.w = fmaf(a0.w, b3.w, acc0.w);

        acc1.x = fmaf(a1.x, b0.x, acc1.x); acc1.y = fmaf(a1.x, b0.y, acc1.y);
        acc1.z = fmaf(a1.x, b0.z, acc1.z); acc1.w = fmaf(a1.x, b0.w, acc1.w);
        acc1.x = fmaf(a1.y, b1.x, acc1.x); acc1.y = fmaf(a1.y, b1.y, acc1.y);
        acc1.z = fmaf(a1.y, b1.z, acc1.z); acc1.w = fmaf(a1.y, b1.w, acc1.w);
        acc1.x = fmaf(a1.z, b2.x, acc1.x); acc1.y = fmaf(a1.z, b2.y, acc1.y);
        acc1.z = fmaf(a1.z, b2.z, acc1.z); acc1.w = fmaf(a1.z, b2.w, acc1.w);
        acc1.x = fmaf(a1.w, b3.x, acc1.x); acc1.y = fmaf(a1.w, b3.y, acc1.y);
        acc1.z = fmaf(a1.w, b3.z, acc1.z); acc1.w = fmaf(a1.w, b3.w, acc1.w);

        acc2.x = fmaf(a2.x, b0.x, acc2.x); acc2.y = fmaf(a2.x, b0.y, acc2.y);
        acc2.z = fmaf(a2.x, b0.z, acc2.z); acc2.w = fmaf(a2.x, b0.w, acc2.w);
        acc2.x = fmaf(a2.y, b1.x, acc2.x); acc2.y = fmaf(a2.y, b1.y, acc2.y);
        acc2.z = fmaf(a2.y, b1.z, acc2.z); acc2.w = fmaf(a2.y, b1.w, acc2.w);
        acc2.x = fmaf(a2.z, b2.x, acc2.x); acc2.y = fmaf(a2.z, b2.y, acc2.y);
        acc2.z = fmaf(a2.z, b2.z, acc2.z); acc2.w = fmaf(a2.z, b2.w, acc2.w);
        acc2.x = fmaf(a2.w, b3.x, acc2.x); acc2.y = fmaf(a2.w, b3.y, acc2.y);
        acc2.z = fmaf(a2.w, b3.z, acc2.z); acc2.w = fmaf(a2.w, b3.w, acc2.w);

        acc3.x = fmaf(a3.x, b0.x, acc3.x); acc3.y = fmaf(a3.x, b0.y, acc3.y);
        acc3.z = fmaf(a3.x, b0.z, acc3.z); acc3.w = fmaf(a3.x, b0.w, acc3.w);
        acc3.x = fmaf(a3.y, b1.x, acc3.x); acc3.y = fmaf(a3.y, b1.y, acc3.y);
        acc3.z = fmaf(a3.y, b1.z, acc3.z); acc3.w = fmaf(a3.y, b1.w, acc3.w);
        acc3.x = fmaf(a3.z, b2.x, acc3.x); acc3.y = fmaf(a3.z, b2.y, acc3.y);
        acc3.z = fmaf(a3.z, b2.z, acc3.z); acc3.w = fmaf(a3.z, b2.w, acc3.w);
        acc3.x = fmaf(a3.w, b3.x, acc3.x); acc3.y = fmaf(a3.w, b3.y, acc3.y);
        acc3.z = fmaf(a3.w, b3.z, acc3.z); acc3.w = fmaf(a3.w, b3.w, acc3.w);
    }
    __syncthreads();
    float4* D4 = reinterpret_cast<float4*>(D);
    D4[(r0 + 0) * 16 + c4] = acc0;
    D4[(r0 + 1) * 16 + c4] = acc1;
    D4[(r0 + 2) * 16 + c4] = acc2;
    D4[(r0 + 3) * 16 + c4] = acc3;
    __syncthreads();
}

// ============================================================================
// prep_a: 1 CTA x 256 threads.  Squares chain + K-vector doubling.
// ============================================================================
__global__ __launch_bounds__(256) void prep_a_kernel(const float* __restrict__ A,
                                                     const float* __restrict__ Bvec) {
    __shared__ __align__(16) float sX[4096];
    __shared__ __align__(16) float sY[4096];
    __shared__ __align__(16) float sK[16 * 64];
    const int t = threadIdx.x;

    for (int i = t; i < 4096; i += 256) sX[i] = A[i];
    if (t < 64) sK[t] = Bvec[t];
    __syncthreads();

    if (t < 64) {                                 // K1 = A K0
        float s = 0.f;
        #pragma unroll
        for (int m = 0; m < 64; m++) s = fmaf(sX[t * 64 + m], sK[m], s);
        sK[64 + t] = s;
    }
    __syncthreads();

    mm64(sX, sX, sY, t);                          // S2
    for (int i = t; i < 4096; i += 256) g_sq[0][i] = sY[i];

    if (t < 128) {                                // K2,K3 = S2 {K0,K1}
        const int v = t >> 6, n = t & 63;
        float s = 0.f;
        #pragma unroll
        for (int m = 0; m < 64; m++) s = fmaf(sY[n * 64 + m], sK[v * 64 + m], s);
        sK[(2 + v) * 64 + n] = s;
    }
    __syncthreads();

    mm64(sY, sY, sX, t);                          // S4
    for (int i = t; i < 4096; i += 256) g_sq[1][i] = sX[i];

    if (t < 256) {                                // K4..7 = S4 K0..3
        const int v = t >> 6, n = t & 63;
        float s = 0.f;
        #pragma unroll
        for (int m = 0; m < 64; m++) s = fmaf(sX[n * 64 + m], sK[v * 64 + m], s);
        sK[(4 + v) * 64 + n] = s;
    }
    __syncthreads();

    mm64(sX, sX, sY, t);                          // S8
    for (int i = t; i < 4096; i += 256) g_sq[2][i] = sY[i];

    {                                             // K8..15 = S8 K0..7 (2 per thread half)
        const int v0 = t >> 6;                    // 0..3
        const int n  = t & 63;
        #pragma unroll
        for (int vv = 0; vv < 2; vv++) {
            const int v = v0 + 4 * vv;            // 0..7
            float s = 0.f;
            #pragma unroll
            for (int m = 0; m < 64; m++) s = fmaf(sY[n * 64 + m], sK[v * 64 + m], s);
            __syncthreads();
            sK[(8 + v) * 64 + n] = s;
        }
    }
    __syncthreads();

    mm64(sY, sY, sX, t);                          // S16
    for (int i = t; i < 4096; i += 256) g_Apow16[i] = sX[i];
    for (int i = t; i < 1024; i += 256) g_Kvec[i] = sK[i];
}

// ============================================================================
// mid_kernel: ONE launch, grid 528 x 256.
//   blocks 0..15   : prep_b  (CTA j builds A^(j+1), writes dense-permuted G)
//   blocks 16..527 : phase1  (4 sequences per block; boundary scan + X build)
// Both depend only on prep_a.
// ============================================================================
__global__ __launch_bounds__(256) void mid_kernel(const float* __restrict__ A,
                                                  const float* __restrict__ xin) {
    __shared__ __align__(16) float sBuf[3][4096];   // 48 KB
    const int t = threadIdx.x;

    if (blockIdx.x < 16) {
        // ---------------- prep_b ----------------
        const int j = blockIdx.x;
        const int p = j + 1;

        const float* fsrc[4];
        int nf = 0;
        if (p == 16) { fsrc[0] = g_sq[2]; fsrc[1] = g_sq[2]; nf = 2; }
        else {
            if (p & 1) fsrc[nf++] = A;
            if (p & 2) fsrc[nf++] = g_sq[0];
            if (p & 4) fsrc[nf++] = g_sq[1];
            if (p & 8) fsrc[nf++] = g_sq[2];
        }

        for (int i = t; i < 4096; i += 256) sBuf[0][i] = fsrc[0][i];
        __syncthreads();

        int cur = 0;
        for (int f = 1; f < nf; f++) {
            for (int i = t; i < 4096; i += 256) sBuf[2][i] = fsrc[f][i];
            __syncthreads();
            mm64(sBuf[cur], sBuf[2], sBuf[cur ^ 1], t);
            cur ^= 1;
        }
        const float* P = sBuf[cur];

        // G rows, DENSE-PERMUTED: pn = 16a+8b+2q+e -> n = 16a+4q+2b+e
        for (int idx = t; idx < 64 * KREAL; idx += 256) {
            const int pn = idx / KREAL, k = idx % KREAL;
            const int a = pn >> 4, b = (pn >> 3) & 1, q = (pn >> 1) & 3, e = pn & 1;
            const int n = 16 * a + 4 * q + 2 * b + e;
            float v;
            if (k < 64) v = P[n * 64 + k];
            else {
                const int d = j - (k - 64);
                v = (d < 0) ? 0.0f : g_Kvec[d * 64 + n];
            }
            g_Gh[(size_t)(j * 64 + pn) * KREAL + k] = __float2half(v);
        }
    } else {
        // ---------------- phase1 (4 sequences per block) ----------------
        const int g   = t >> 6;           // subgroup 0..3
        const int n   = t & 63;
        const int seq = (blockIdx.x - 16) * 4 + g;

        float* c_sm = sBuf[0];            // [2][4][64] = 512 floats
        float* f_sm = sBuf[0] + 512;      // [2][4][16] = 128 floats

        double a16[32];
        {
            const double* r = reinterpret_cast<const double*>(&g_Apow16[n * 64]);
            #pragma unroll
            for (int i = 0; i < 32; i++) a16[i] = r[i];
        }
        double wp[8];
        #pragma unroll
        for (int i = 0; i < 8; i++)
            wp[i] = pack2(g_Kvec[(15 - 2 * i) * 64 + n], g_Kvec[(14 - 2 * i) * 64 + n]);

        float cmy = 0.0f;
        c_sm[g * 64 + n] = 0.0f;

        for (int k = 0; k < NCHUNK; k++) {
            const int buf = k & 1;
            const size_t col = (size_t)k * NSEQ + seq;
            g_Xh[col * KREAL + n] = __float2half(cmy);
            if (n < 16) {
                const float f = xin[(size_t)seq * SEQLEN + k * TCH + n];
                f_sm[buf * 64 + g * 16 + n] = f;
                g_Xh[col * KREAL + 64 + n] = __float2half(f);
            }
            __syncthreads();

            const double2* cp = reinterpret_cast<const double2*>(c_sm + buf * 256 + g * 64);
            double acc0 = 0.0, acc1 = 0.0, acc2 = 0.0, acc3 = 0.0;
            #pragma unroll
            for (int i = 0; i < 8; i++) {
                const double2 ca = cp[2 * i], cb = cp[2 * i + 1];
                acc0 = fma2(a16[4 * i],     ca.x, acc0);
                acc1 = fma2(a16[4 * i + 1], ca.y, acc1);
                acc2 = fma2(a16[4 * i + 2], cb.x, acc2);
                acc3 = fma2(a16[4 * i + 3], cb.y, acc3);
            }
            const double* fp = reinterpret_cast<const double*>(f_sm + buf * 64 + g * 16);
            acc0 = fma2(wp[0], fp[0], acc0); acc1 = fma2(wp[1], fp[1], acc1);
            acc2 = fma2(wp[2], fp[2], acc2); acc3 = fma2(wp[3], fp[3], acc3);
            acc0 = fma2(wp[4], fp[4], acc0); acc1 = fma2(wp[5], fp[5], acc1);
            acc2 = fma2(wp[6], fp[6], acc2); acc3 = fma2(wp[7], fp[7], acc3);

            const double s = add2(add2(acc0, acc1), add2(acc2, acc3));
            float x, y;
            unpack2(s, x, y);
            cmy = x + y;
            c_sm[(buf ^ 1) * 256 + g * 64 + n] = cmy;
        }
    }
}

// ============================================================================
// GEMM: grid (512, 8) x 256 thr, __launch_bounds__(256, 3).
// CTA: 128 X-cols x 2 jt, ONE barrier.
// Arena 45056 B: [Xh 22528 | G(j0) 11264 | G(j0+1) 11264].
// Dense-permuted G: lane quads write contiguous 64B blocks (full sectors).
// ============================================================================
__global__ __launch_bounds__(256, 3) void gemm_kernel(float* __restrict__ out) {
    __shared__ __align__(16) char arena[45056];

    const int tid = threadIdx.x;
    const int w = tid >> 5, l = tid & 31;
    const int mbase = blockIdx.x * MT;
    const int j0    = blockIdx.y * 2;
    const uint32_t base = smem_u32(arena);

    for (int c = tid; c < 1280; c += 256) {
        const int row = c / 10, part = c % 10;
        cp_async16(base + row * KPADB + part * 16,
                   (const char*)(g_Xh + (size_t)(mbase + row) * KREAL) + part * 16);
    }
    for (int c = tid; c < 1280; c += 256) {
        const int g = c / 640, rem = c % 640;
        const int row = rem / 10, part = rem % 10;
        cp_async16(base + 22528 + g * 11264 + row * KPADB + part * 16,
                   (const char*)(g_Gh + (size_t)((j0 + g) * 64 + row) * KREAL) + part * 16);
    }
    cp_commit(); cp_wait0();
    __syncthreads();

    const int jl = w >> 2;
    const int mq = w & 3;
    const int jt = j0 + jl;

    const uint32_t aoff = base + (uint32_t)(mq * 32 + (l & 15)) * KPADB + ((l >> 4) * 16);
    const uint32_t gbuf = base + 22528 + jl * 11264;
    const uint32_t boff = gbuf + (uint32_t)((l & 7) + ((l & 16) >> 1)) * KPADB + ((l & 8) << 1);

    float acc[2][8][4];
    #pragma unroll
    for (int mt = 0; mt < 2; mt++)
        #pragma unroll
        for (int nt = 0; nt < 8; nt++)
            #pragma unroll
            for (int q = 0; q < 4; q++) acc[mt][nt][q] = 0.0f;

    #pragma unroll
    for (int ks = 0; ks < 5; ks++) {
        uint32_t bh[4][4];
        #pragma unroll
        for (int p = 0; p < 4; p++)
            ldsm_x4(bh[p], boff + p * (16 * KPADB) + ks * 32);
        #pragma unroll
        for (int mt = 0; mt < 2; mt++) {
            uint32_t a4[4];
            ldsm_x4(a4, aoff + mt * (16 * KPADB) + ks * 32);
            #pragma unroll
            for (int p = 0; p < 4; p++)
                #pragma unroll
                for (int hh = 0; hh < 2; hh++)
                    mma16816(acc[mt][p * 2 + hh], a4, bh[p][2 * hh], bh[p][2 * hh + 1]);
        }
    }

    // ---- epilogue: dense 64B quad blocks ----
    const int chunk = mbase >> 11;
    const int seqb  = mbase & 2047;
    const int q     = l & 3;
    float* obase = out + (size_t)(chunk * TCH + jt) * NSEQ * 64 + 4 * q;
    #pragma unroll
    for (int mt = 0; mt < 2; mt++)
        #pragma unroll
        for (int s = 0; s < 2; s++) {
            const int m = mq * 32 + mt * 16 + (l >> 2) + s * 8;
            float* ob = obase + (size_t)(seqb + m) * 64;
            #pragma unroll
            for (int a = 0; a < 4; a++) {
                float4 v = make_float4(acc[mt][2 * a][2 * s],
                                       acc[mt][2 * a][2 * s + 1],
                                       acc[mt][2 * a + 1][2 * s],
                                       acc[mt][2 * a + 1][2 * s + 1]);
                __stcs(reinterpret_cast<float4*>(ob + 16 * a), v);
            }
        }
}

// ============================================================================
extern "C" void kernel_launch(void* const* d_in, const int* in_sizes, int n_in,
                              void* d_out, int out_size) {
    const float* xin  = (const float*)d_in[0];  // (16,128,512)
    const float* Amat = (const float*)d_in[1];  // (64,64)
    const float* Bvec = (const float*)d_in[2];  // (64,)
    float* out = (float*)d_out;                 // (512,16,128,64)

    prep_a_kernel<<<1, 256>>>(Amat, Bvec);
    mid_kernel<<<16 + NSEQ / 4, 256>>>(Amat, xin);
    dim3 ggrid(NCOLS / MT, 8);                  // (512, 8)
    gemm_kernel<<<ggrid, 256>>>(out);
}